// round 1
// baseline (speedup 1.0000x reference)
#include <cuda_runtime.h>
#include <math.h>

// LocalAggregator: relational graph-attention aggregation.
// out = softmax_j( mask(adj, leakyrelu( (h_i ⊙ W_k) · h_j + b_k )) ) @ H
// with k = adj[i,j]-1, masked (adj==0) -> -9e15.
//
// Design: fused flash-style kernel.
//   - block handles BM=32 rows i; A-matrix rows m = i_local*4 + k (M'=128)
//   - loop over 32 j-tiles of BN=128; S tile = 128x128x128 fp32 register GEMM
//   - 8x8 micro-tile per thread; k interleaved fastest so each thread holds
//     all 4 k-scores of its (i,j) pairs in registers -> selection is a
//     register select chain (no dynamic register indexing, no smem roundtrip)
//   - online softmax (exact), p-tile through smem, fused AV GEMM.

#define NNODES 4096
#define DIMD   128
#define BM     32
#define BN     128
#define NT     256

#define SA_ELEMS (128*128)       // hw tile, [d][m], m = il*4+k
#define SB_ELEMS (128*128)       // h_j tile, [d][j]
#define SBT_LD   132
#define SBT_ELEMS (128*SBT_LD)   // h_j tile, [j][d] padded
#define SP_LD    129
#define SP_ELEMS (BM*SP_LD)      // p tile, [i][j] padded
#define SMEM_BYTES ((SA_ELEMS + SB_ELEMS + SBT_ELEMS + SP_ELEMS)*4 + BM*BN)

__global__ __launch_bounds__(NT, 1)
void agg_kernel(const float* __restrict__ H, const int* __restrict__ ADJ,
                const float* __restrict__ W, const float* __restrict__ Bv,
                float* __restrict__ OUT) {
    extern __shared__ float sm[];
    float* sA  = sm;                       // 64 KB
    float* sB  = sA + SA_ELEMS;            // 64 KB
    float* sBt = sB + SB_ELEMS;            // 66 KB
    float* sP  = sBt + SBT_ELEMS;          // 16.1 KB
    unsigned char* sAdj = (unsigned char*)(sP + SP_ELEMS);  // 4 KB

    const int tid = threadIdx.x;
    const int tx  = tid & 15;   // j / dd direction (16)
    const int ty  = tid >> 4;   // m / i direction  (16)
    const int i0  = blockIdx.x * BM;

    const float bb0 = Bv[0], bb1 = Bv[1], bb2 = Bv[2], bb3 = Bv[3];

    // Build sA[d][m] = H[i0+il][d] * W[k][d],  m = il*4 + k
    #pragma unroll
    for (int t = 0; t < SA_ELEMS/NT; ++t) {
        int e = t*NT + tid;
        int d = e >> 7;
        int m = e & 127;
        int il = m >> 2;
        int k  = m & 3;
        sA[e] = H[(i0+il)*DIMD + d] * W[k*DIMD + d];
    }

    float mrow[2] = {-INFINITY, -INFINITY};
    float lrow[2] = {0.f, 0.f};
    float Oacc[2][8];
    #pragma unroll
    for (int u = 0; u < 2; ++u)
        #pragma unroll
        for (int v = 0; v < 8; ++v) Oacc[u][v] = 0.f;

    for (int jt = 0; jt < NNODES/BN; ++jt) {
        const int j0 = jt * BN;
        __syncthreads();   // previous AV done (and sA ready on first iter)

        // Load h_j tile into both layouts + adj tile
        #pragma unroll
        for (int t = 0; t < (BN*DIMD/4)/NT; ++t) {   // 16 float4 per thread
            int idx = t*NT + tid;
            int jj  = idx >> 5;        // 32 float4 per row
            int d   = (idx & 31) * 4;
            float4 v = *reinterpret_cast<const float4*>(&H[(j0+jj)*DIMD + d]);
            *reinterpret_cast<float4*>(&sBt[jj*SBT_LD + d]) = v;
            sB[(d+0)*BN + jj] = v.x;
            sB[(d+1)*BN + jj] = v.y;
            sB[(d+2)*BN + jj] = v.z;
            sB[(d+3)*BN + jj] = v.w;
        }
        #pragma unroll
        for (int t = 0; t < (BM*BN)/NT; ++t) {       // 16 per thread
            int idx = t*NT + tid;
            int il  = idx >> 7;
            int jj  = idx & 127;
            sAdj[idx] = (unsigned char)ADJ[(i0+il)*NNODES + j0 + jj];
        }
        __syncthreads();

        // S-GEMM: acc[u][v], rows m = ty*8+u (il = 2ty + (u>>2), k = u&3)
        float acc[8][8];
        #pragma unroll
        for (int u = 0; u < 8; ++u)
            #pragma unroll
            for (int v = 0; v < 8; ++v) acc[u][v] = 0.f;

        #pragma unroll 4
        for (int d = 0; d < DIMD; ++d) {
            float a8[8], b8[8];
            *reinterpret_cast<float4*>(&a8[0]) = *reinterpret_cast<const float4*>(&sA[d*128 + ty*8]);
            *reinterpret_cast<float4*>(&a8[4]) = *reinterpret_cast<const float4*>(&sA[d*128 + ty*8 + 4]);
            *reinterpret_cast<float4*>(&b8[0]) = *reinterpret_cast<const float4*>(&sB[d*BN + tx*8]);
            *reinterpret_cast<float4*>(&b8[4]) = *reinterpret_cast<const float4*>(&sB[d*BN + tx*8 + 4]);
            #pragma unroll
            for (int u = 0; u < 8; ++u)
                #pragma unroll
                for (int v = 0; v < 8; ++v)
                    acc[u][v] = fmaf(a8[u], b8[v], acc[u][v]);
        }

        // Selection + leakyrelu + mask + online softmax (rows i = 2ty+u2)
        #pragma unroll
        for (int u2 = 0; u2 < 2; ++u2) {
            const int il = 2*ty + u2;
            float pv[8];
            float tmax = -INFINITY;
            #pragma unroll
            for (int v = 0; v < 8; ++v) {
                int a = (int)sAdj[il*BN + tx*8 + v];
                float s0 = acc[u2*4+0][v] + bb0;
                float s1 = acc[u2*4+1][v] + bb1;
                float s2 = acc[u2*4+2][v] + bb2;
                float s3 = acc[u2*4+3][v] + bb3;
                float s  = (a==1) ? s0 : (a==2) ? s1 : (a==3) ? s2 : s3;
                s = (s > 0.f) ? s : 0.2f*s;          // leakyrelu(0.2)
                float val = (a == 0) ? -9e15f : s;   // mask
                pv[v] = val;
                tmax  = fmaxf(tmax, val);
            }
            // reduce over the 16 tx lanes (stays within 16-lane half-warp)
            #pragma unroll
            for (int off = 8; off >= 1; off >>= 1)
                tmax = fmaxf(tmax, __shfl_xor_sync(0xffffffffu, tmax, off));

            float mnew  = fmaxf(mrow[u2], tmax);
            float scale = expf(mrow[u2] - mnew);     // expf(-inf)=0 on first tile
            float rsum = 0.f;
            #pragma unroll
            for (int v = 0; v < 8; ++v) {
                float p = expf(pv[v] - mnew);
                pv[v] = p;
                rsum += p;
            }
            #pragma unroll
            for (int off = 8; off >= 1; off >>= 1)
                rsum += __shfl_xor_sync(0xffffffffu, rsum, off);

            lrow[u2] = lrow[u2]*scale + rsum;
            #pragma unroll
            for (int v = 0; v < 8; ++v) Oacc[u2][v] *= scale;
            mrow[u2] = mnew;

            #pragma unroll
            for (int v = 0; v < 8; ++v)
                sP[il*SP_LD + tx*8 + v] = pv[v];
        }
        __syncthreads();

        // AV: O[i][dd] += sum_j p[i][j] * h[j][dd],  dd = tx*8+v
        #pragma unroll 4
        for (int jj = 0; jj < BN; ++jj) {
            float p0 = sP[(2*ty  )*SP_LD + jj];
            float p1 = sP[(2*ty+1)*SP_LD + jj];
            float hb[8];
            *reinterpret_cast<float4*>(&hb[0]) = *reinterpret_cast<const float4*>(&sBt[jj*SBT_LD + tx*8]);
            *reinterpret_cast<float4*>(&hb[4]) = *reinterpret_cast<const float4*>(&sBt[jj*SBT_LD + tx*8 + 4]);
            #pragma unroll
            for (int v = 0; v < 8; ++v) {
                Oacc[0][v] = fmaf(p0, hb[v], Oacc[0][v]);
                Oacc[1][v] = fmaf(p1, hb[v], Oacc[1][v]);
            }
        }
    }

    // Epilogue: normalize and store
    #pragma unroll
    for (int u2 = 0; u2 < 2; ++u2) {
        const int il = 2*ty + u2;
        float inv = 1.f / lrow[u2];
        float outv[8];
        #pragma unroll
        for (int v = 0; v < 8; ++v) outv[v] = Oacc[u2][v] * inv;
        float* dst = &OUT[(i0+il)*DIMD + tx*8];
        *reinterpret_cast<float4*>(dst)     = *reinterpret_cast<float4*>(&outv[0]);
        *reinterpret_cast<float4*>(dst + 4) = *reinterpret_cast<float4*>(&outv[4]);
    }
}

extern "C" void kernel_launch(void* const* d_in, const int* in_sizes, int n_in,
                              void* d_out, int out_size) {
    // Identify inputs by element count (all four sizes distinct).
    const float* H = nullptr; const int* ADJ = nullptr;
    const float* W = nullptr; const float* Bv = nullptr;
    for (int i = 0; i < n_in; ++i) {
        switch (in_sizes[i]) {
            case NNODES*DIMD:   H   = (const float*)d_in[i]; break;
            case NNODES*NNODES: ADJ = (const int*)  d_in[i]; break;
            case 4*DIMD:        W   = (const float*)d_in[i]; break;
            case 4:             Bv  = (const float*)d_in[i]; break;
        }
    }
    // Idempotent, not a stream op -> capture-safe.
    cudaFuncSetAttribute(agg_kernel, cudaFuncAttributeMaxDynamicSharedMemorySize, SMEM_BYTES);
    agg_kernel<<<NNODES/BM, NT, SMEM_BYTES>>>(H, ADJ, W, Bv, (float*)d_out);
}

// round 2
// speedup vs baseline: 1.0572x; 1.0572x over previous
#include <cuda_runtime.h>
#include <math.h>

// LocalAggregator: relational graph-attention aggregation.
// out = softmax_j( mask(adj, leakyrelu( (h_i ⊙ W_k) · h_j + b_k )) ) @ H
// with k = adj[i,j]-1, masked (adj==0) -> -9e15.
//
// Design: fused flash-style kernel.
//   - block handles BM=32 rows i; A-matrix rows m = i_local*4 + k (M'=128)
//   - loop over 32 j-tiles of BN=128; S tile = 128x128x128 fp32 register GEMM
//   - 8x8 micro-tile per thread; k interleaved fastest so each thread holds
//     all 4 k-scores of its (i,j) pairs in registers -> selection is a
//     register select chain (no dynamic register indexing, no smem roundtrip)
//   - online softmax (exact), p-tile through smem, fused AV GEMM.

#define NNODES 4096
#define DIMD   128
#define BM     32
#define BN     128
#define NT     256

#define SA_ELEMS (128*128)       // hw tile, [d][m], m = il*4+k
#define SB_ELEMS (128*128)       // h_j tile, [d][j]
#define SBT_LD   132
#define SBT_ELEMS (128*SBT_LD)   // h_j tile, [j][d] padded
#define SP_LD    129
#define SP_ELEMS (BM*SP_LD)      // p tile, [i][j] padded
#define SMEM_BYTES ((SA_ELEMS + SB_ELEMS + SBT_ELEMS + SP_ELEMS)*4 + BM*BN)

__global__ __launch_bounds__(NT, 1)
void agg_kernel(const float* __restrict__ H, const int* __restrict__ ADJ,
                const float* __restrict__ W, const float* __restrict__ Bv,
                float* __restrict__ OUT) {
    extern __shared__ float sm[];
    float* sA  = sm;                       // 64 KB
    float* sB  = sA + SA_ELEMS;            // 64 KB
    float* sBt = sB + SB_ELEMS;            // 66 KB
    float* sP  = sBt + SBT_ELEMS;          // 16.1 KB
    unsigned char* sAdj = (unsigned char*)(sP + SP_ELEMS);  // 4 KB

    const int tid = threadIdx.x;
    const int tx  = tid & 15;   // j / dd direction (16)
    const int ty  = tid >> 4;   // m / i direction  (16)
    const int i0  = blockIdx.x * BM;

    const float bb0 = Bv[0], bb1 = Bv[1], bb2 = Bv[2], bb3 = Bv[3];

    // Build sA[d][m] = H[i0+il][d] * W[k][d],  m = il*4 + k
    #pragma unroll
    for (int t = 0; t < SA_ELEMS/NT; ++t) {
        int e = t*NT + tid;
        int d = e >> 7;
        int m = e & 127;
        int il = m >> 2;
        int k  = m & 3;
        sA[e] = H[(i0+il)*DIMD + d] * W[k*DIMD + d];
    }

    float mrow[2] = {-INFINITY, -INFINITY};
    float lrow[2] = {0.f, 0.f};
    float Oacc[2][8];
    #pragma unroll
    for (int u = 0; u < 2; ++u)
        #pragma unroll
        for (int v = 0; v < 8; ++v) Oacc[u][v] = 0.f;

    for (int jt = 0; jt < NNODES/BN; ++jt) {
        const int j0 = jt * BN;
        __syncthreads();   // previous AV done (and sA ready on first iter)

        // Load h_j tile into both layouts + adj tile
        #pragma unroll
        for (int t = 0; t < (BN*DIMD/4)/NT; ++t) {   // 16 float4 per thread
            int idx = t*NT + tid;
            int jj  = idx >> 5;        // 32 float4 per row
            int d   = (idx & 31) * 4;
            float4 v = *reinterpret_cast<const float4*>(&H[(j0+jj)*DIMD + d]);
            *reinterpret_cast<float4*>(&sBt[jj*SBT_LD + d]) = v;
            sB[(d+0)*BN + jj] = v.x;
            sB[(d+1)*BN + jj] = v.y;
            sB[(d+2)*BN + jj] = v.z;
            sB[(d+3)*BN + jj] = v.w;
        }
        #pragma unroll
        for (int t = 0; t < (BM*BN)/NT; ++t) {       // 16 per thread
            int idx = t*NT + tid;
            int il  = idx >> 7;
            int jj  = idx & 127;
            sAdj[idx] = (unsigned char)ADJ[(i0+il)*NNODES + j0 + jj];
        }
        __syncthreads();

        // S-GEMM: acc[u][v], rows m = ty*8+u (il = 2ty + (u>>2), k = u&3)
        float acc[8][8];
        #pragma unroll
        for (int u = 0; u < 8; ++u)
            #pragma unroll
            for (int v = 0; v < 8; ++v) acc[u][v] = 0.f;

        #pragma unroll 4
        for (int d = 0; d < DIMD; ++d) {
            float a8[8], b8[8];
            *reinterpret_cast<float4*>(&a8[0]) = *reinterpret_cast<const float4*>(&sA[d*128 + ty*8]);
            *reinterpret_cast<float4*>(&a8[4]) = *reinterpret_cast<const float4*>(&sA[d*128 + ty*8 + 4]);
            *reinterpret_cast<float4*>(&b8[0]) = *reinterpret_cast<const float4*>(&sB[d*BN + tx*8]);
            *reinterpret_cast<float4*>(&b8[4]) = *reinterpret_cast<const float4*>(&sB[d*BN + tx*8 + 4]);
            #pragma unroll
            for (int u = 0; u < 8; ++u)
                #pragma unroll
                for (int v = 0; v < 8; ++v)
                    acc[u][v] = fmaf(a8[u], b8[v], acc[u][v]);
        }

        // Selection + leakyrelu + mask + online softmax (rows i = 2ty+u2)
        #pragma unroll
        for (int u2 = 0; u2 < 2; ++u2) {
            const int il = 2*ty + u2;
            float pv[8];
            float tmax = -INFINITY;
            #pragma unroll
            for (int v = 0; v < 8; ++v) {
                int a = (int)sAdj[il*BN + tx*8 + v];
                float s0 = acc[u2*4+0][v] + bb0;
                float s1 = acc[u2*4+1][v] + bb1;
                float s2 = acc[u2*4+2][v] + bb2;
                float s3 = acc[u2*4+3][v] + bb3;
                float s  = (a==1) ? s0 : (a==2) ? s1 : (a==3) ? s2 : s3;
                s = (s > 0.f) ? s : 0.2f*s;          // leakyrelu(0.2)
                float val = (a == 0) ? -9e15f : s;   // mask
                pv[v] = val;
                tmax  = fmaxf(tmax, val);
            }
            // reduce over the 16 tx lanes (stays within 16-lane half-warp)
            #pragma unroll
            for (int off = 8; off >= 1; off >>= 1)
                tmax = fmaxf(tmax, __shfl_xor_sync(0xffffffffu, tmax, off));

            float mnew  = fmaxf(mrow[u2], tmax);
            float scale = expf(mrow[u2] - mnew);     // expf(-inf)=0 on first tile
            float rsum = 0.f;
            #pragma unroll
            for (int v = 0; v < 8; ++v) {
                float p = expf(pv[v] - mnew);
                pv[v] = p;
                rsum += p;
            }
            #pragma unroll
            for (int off = 8; off >= 1; off >>= 1)
                rsum += __shfl_xor_sync(0xffffffffu, rsum, off);

            lrow[u2] = lrow[u2]*scale + rsum;
            #pragma unroll
            for (int v = 0; v < 8; ++v) Oacc[u2][v] *= scale;
            mrow[u2] = mnew;

            #pragma unroll
            for (int v = 0; v < 8; ++v)
                sP[il*SP_LD + tx*8 + v] = pv[v];
        }
        __syncthreads();

        // AV: O[i][dd] += sum_j p[i][j] * h[j][dd],  dd = tx*8+v
        #pragma unroll 4
        for (int jj = 0; jj < BN; ++jj) {
            float p0 = sP[(2*ty  )*SP_LD + jj];
            float p1 = sP[(2*ty+1)*SP_LD + jj];
            float hb[8];
            *reinterpret_cast<float4*>(&hb[0]) = *reinterpret_cast<const float4*>(&sBt[jj*SBT_LD + tx*8]);
            *reinterpret_cast<float4*>(&hb[4]) = *reinterpret_cast<const float4*>(&sBt[jj*SBT_LD + tx*8 + 4]);
            #pragma unroll
            for (int v = 0; v < 8; ++v) {
                Oacc[0][v] = fmaf(p0, hb[v], Oacc[0][v]);
                Oacc[1][v] = fmaf(p1, hb[v], Oacc[1][v]);
            }
        }
    }

    // Epilogue: normalize and store
    #pragma unroll
    for (int u2 = 0; u2 < 2; ++u2) {
        const int il = 2*ty + u2;
        float inv = 1.f / lrow[u2];
        float outv[8];
        #pragma unroll
        for (int v = 0; v < 8; ++v) outv[v] = Oacc[u2][v] * inv;
        float* dst = &OUT[(i0+il)*DIMD + tx*8];
        *reinterpret_cast<float4*>(dst)     = *reinterpret_cast<float4*>(&outv[0]);
        *reinterpret_cast<float4*>(dst + 4) = *reinterpret_cast<float4*>(&outv[4]);
    }
}

extern "C" void kernel_launch(void* const* d_in, const int* in_sizes, int n_in,
                              void* d_out, int out_size) {
    // Identify inputs by element count (all four sizes distinct).
    const float* H = nullptr; const int* ADJ = nullptr;
    const float* W = nullptr; const float* Bv = nullptr;
    for (int i = 0; i < n_in; ++i) {
        switch (in_sizes[i]) {
            case NNODES*DIMD:   H   = (const float*)d_in[i]; break;
            case NNODES*NNODES: ADJ = (const int*)  d_in[i]; break;
            case 4*DIMD:        W   = (const float*)d_in[i]; break;
            case 4:             Bv  = (const float*)d_in[i]; break;
        }
    }
    // Idempotent, not a stream op -> capture-safe.
    cudaFuncSetAttribute(agg_kernel, cudaFuncAttributeMaxDynamicSharedMemorySize, SMEM_BYTES);
    agg_kernel<<<NNODES/BM, NT, SMEM_BYTES>>>(H, ADJ, W, Bv, (float*)d_out);
}

// round 4
// speedup vs baseline: 3.1242x; 2.9552x over previous
#include <cuda_runtime.h>
#include <math.h>
#include <stdint.h>

#define NN 4096
#define DD 128
#define BM 128
#define BN 32
#define NSPLIT 4
#define JSPAN (NN/NSPLIT)
#define TILES (JSPAN/BN)
#define NT 256
#define RS1 144          // row stride (floats) for A/B1 swizzled layout

// float-index smem offsets
#define OFF_A    0
#define OFF_B1   (128*RS1)            // 18432
#define OFF_B2   (2*128*RS1)          // 36864
#define OFF_P    (OFF_B2 + 128*33)    // 41088
#define OFF_W    (OFF_P + 128*33)     // 45312
#define OFF_RMAX (OFF_W + 512)        // 45824
#define OFF_RSUM (OFF_RMAX + 256)     // 46080
#define OFF_ADJ  (OFF_RSUM + 256)     // adj bytes live here (4096 B = 1024 floats)
#define SMEM_FLOATS (OFF_ADJ + 1024)
#define SMEM_BYTES (SMEM_FLOATS*4)    // 189440

__device__ float g_Opart[(size_t)NSPLIT*NN*DD];
__device__ float g_m[NSPLIT*NN];
__device__ float g_l[NSPLIT*NN];

__device__ __forceinline__ uint32_t f2tf32(float x) {
    uint32_t r; asm("cvt.rna.tf32.f32 %0, %1;" : "=r"(r) : "f"(x)); return r;
}
__device__ __forceinline__ void mma8(float* d, uint32_t a0, uint32_t a1, uint32_t a2, uint32_t a3,
                                     uint32_t b0, uint32_t b1) {
    asm volatile("mma.sync.aligned.m16n8k8.row.col.f32.tf32.tf32.f32 "
        "{%0,%1,%2,%3},{%4,%5,%6,%7},{%8,%9},{%0,%1,%2,%3};"
        : "+f"(d[0]), "+f"(d[1]), "+f"(d[2]), "+f"(d[3])
        : "r"(a0), "r"(a1), "r"(a2), "r"(a3), "r"(b0), "r"(b1));
}

__global__ __launch_bounds__(NT, 1)
void agg1(const float* __restrict__ H, const int* __restrict__ ADJ,
          const float* __restrict__ W, const float* __restrict__ Bv) {
    extern __shared__ float sm[];
    uint32_t* smb = reinterpret_cast<uint32_t*>(sm);
    unsigned char* sAdjB = reinterpret_cast<unsigned char*>(sm + OFF_ADJ);
    float* redmax = sm + OFF_RMAX;
    float* redsum = sm + OFF_RSUM;

    const int tid = threadIdx.x, wid = tid >> 5, lane = tid & 31;
    const int g = lane >> 2, c2 = lane & 3;       // fragment coords
    const int rb = wid & 3, cb = wid >> 2;        // warp grid 4 (rows) x 2 (cols)
    const int itile = blockIdx.x & 31, split = blockIdx.x >> 5;
    const int i0 = itile * BM, jbase = split * JSPAN;

    // W -> smem
    for (int e = tid; e < 4 * DD; e += NT) sm[OFF_W + e] = W[e];

    // A tile (H_i, tf32) in swizzled layout: row i, u = (d&3)*36 + (d>>2)
    {
        const int ir = tid >> 1, half = tid & 1;
        const float* hr = H + (size_t)(i0 + ir) * DD;
        #pragma unroll
        for (int it = 0; it < 16; ++it) {
            int itr = (it + ir) & 15;           // stagger -> conflict-free STS
            int q = 16 * half + itr;            // q = d>>2
            float4 v = *reinterpret_cast<const float4*>(hr + 4 * q);
            uint32_t* dst = smb + OFF_A + ir * RS1 + q;
            dst[0] = f2tf32(v.x); dst[36] = f2tf32(v.y);
            dst[72] = f2tf32(v.z); dst[108] = f2tf32(v.w);
        }
    }
    __syncthreads();

    const float bb0 = Bv[0], bb1 = Bv[1], bb2 = Bv[2], bb3 = Bv[3];
    float mrun[2][2], lrun[2][2];
    #pragma unroll
    for (int a = 0; a < 2; ++a)
        #pragma unroll
        for (int b = 0; b < 2; ++b) { mrun[a][b] = -INFINITY; lrun[a][b] = 0.f; }
    float Of[2][8][4];
    #pragma unroll
    for (int mf = 0; mf < 2; ++mf)
        #pragma unroll
        for (int nf = 0; nf < 8; ++nf)
            #pragma unroll
            for (int e = 0; e < 4; ++e) Of[mf][nf][e] = 0.f;

    for (int tt = 0; tt < TILES; ++tt) {
        const int j0 = jbase + tt * BN;
        __syncthreads();   // prev AV reads done before overwriting B1/B2/adj

        // ---- prep B1: row n' = k*32+j, val = tf32(H[j][d]*W[k][d])
        {
            const int n_ = tid >> 1, half = tid & 1, j = n_ & 31, k = n_ >> 5;
            const float* hr = H + (size_t)(j0 + j) * DD;
            const float* wr = sm + OFF_W + k * DD;
            #pragma unroll
            for (int it = 0; it < 16; ++it) {
                int itr = (it + n_) & 15;
                int q = 16 * half + itr;
                float4 hv = *reinterpret_cast<const float4*>(hr + 4 * q);
                float4 wv = *reinterpret_cast<const float4*>(wr + 4 * q);
                uint32_t* dst = smb + OFF_B1 + n_ * RS1 + q;
                dst[0] = f2tf32(hv.x * wv.x); dst[36] = f2tf32(hv.y * wv.y);
                dst[72] = f2tf32(hv.z * wv.z); dst[108] = f2tf32(hv.w * wv.w);
            }
        }
        // ---- prep B2: H^T [dd][j], stride 33
        {
            const int j = tid & 31, dg = tid >> 5;
            const float* hr = H + (size_t)(j0 + j) * DD + dg * 16;
            #pragma unroll
            for (int q = 0; q < 4; ++q) {
                float4 v = *reinterpret_cast<const float4*>(hr + 4 * q);
                int d = dg * 16 + 4 * q;
                smb[OFF_B2 + (d + 0) * 33 + j] = f2tf32(v.x);
                smb[OFF_B2 + (d + 1) * 33 + j] = f2tf32(v.y);
                smb[OFF_B2 + (d + 2) * 33 + j] = f2tf32(v.z);
                smb[OFF_B2 + (d + 3) * 33 + j] = f2tf32(v.w);
            }
        }
        // ---- adj tile -> bytes
        {
            const int i = tid >> 1, half = tid & 1;
            const int* ar = ADJ + (size_t)(i0 + i) * NN + j0 + half * 16;
            uint32_t* dst = reinterpret_cast<uint32_t*>(sAdjB + i * 32 + half * 16);
            #pragma unroll
            for (int q = 0; q < 4; ++q) {
                int4 w4 = reinterpret_cast<const int4*>(ar)[q];
                dst[q] = (uint32_t)w4.x | ((uint32_t)w4.y << 8) |
                         ((uint32_t)w4.z << 16) | ((uint32_t)w4.w << 24);
            }
        }
        __syncthreads();   // operands ready

        // ---- S GEMM: 4 k-accumulator sets
        float acc[4][2][2][4];
        #pragma unroll
        for (int k = 0; k < 4; ++k)
            #pragma unroll
            for (int mf = 0; mf < 2; ++mf)
                #pragma unroll
                for (int nf = 0; nf < 2; ++nf)
                    #pragma unroll
                    for (int e = 0; e < 4; ++e) acc[k][mf][nf][e] = 0.f;

        #pragma unroll
        for (int kc = 0; kc < 8; ++kc) {
            uint4 aA[4];
            #pragma unroll
            for (int rg = 0; rg < 4; ++rg)
                aA[rg] = *reinterpret_cast<const uint4*>(
                    smb + OFF_A + (rb * 32 + rg * 8 + g) * RS1 + c2 * 36 + 4 * kc);
            uint4 bB[4][2];
            #pragma unroll
            for (int k = 0; k < 4; ++k)
                #pragma unroll
                for (int nf = 0; nf < 2; ++nf)
                    bB[k][nf] = *reinterpret_cast<const uint4*>(
                        smb + OFF_B1 + (k * 32 + cb * 16 + nf * 8 + g) * RS1 + c2 * 36 + 4 * kc);
            #pragma unroll
            for (int k = 0; k < 4; ++k)
                #pragma unroll
                for (int mf = 0; mf < 2; ++mf)
                    #pragma unroll
                    for (int nf = 0; nf < 2; ++nf) {
                        mma8(acc[k][mf][nf], aA[2*mf].x, aA[2*mf+1].x, aA[2*mf].y, aA[2*mf+1].y,
                             bB[k][nf].x, bB[k][nf].y);
                        mma8(acc[k][mf][nf], aA[2*mf].z, aA[2*mf+1].z, aA[2*mf].w, aA[2*mf+1].w,
                             bB[k][nf].z, bB[k][nf].w);
                    }
        }

        // ---- selection + leaky + mask + online softmax
        float pv[2][2][4], tmax[2][2] = {{-INFINITY, -INFINITY}, {-INFINITY, -INFINITY}};
        #pragma unroll
        for (int mf = 0; mf < 2; ++mf)
            #pragma unroll
            for (int nf = 0; nf < 2; ++nf)
                #pragma unroll
                for (int e = 0; e < 4; ++e) {
                    const int h2 = e >> 1, jj = e & 1;
                    const int iL = rb * 32 + mf * 16 + h2 * 8 + g;
                    const int jL = cb * 16 + nf * 8 + 2 * c2 + jj;
                    int a = (int)sAdjB[iL * 32 + jL];
                    float s0 = acc[0][mf][nf][e] + bb0;
                    float s1 = acc[1][mf][nf][e] + bb1;
                    float s2 = acc[2][mf][nf][e] + bb2;
                    float s3 = acc[3][mf][nf][e] + bb3;
                    float s = (a == 1) ? s0 : (a == 2) ? s1 : (a == 3) ? s2 : s3;
                    s = (s > 0.f) ? s : 0.2f * s;
                    float val = (a == 0) ? -9e15f : s;
                    pv[mf][nf][e] = val;
                    tmax[mf][h2] = fmaxf(tmax[mf][h2], val);
                }
        #pragma unroll
        for (int mf = 0; mf < 2; ++mf)
            #pragma unroll
            for (int h2 = 0; h2 < 2; ++h2) {
                float t = tmax[mf][h2];
                t = fmaxf(t, __shfl_xor_sync(0xffffffffu, t, 1));
                t = fmaxf(t, __shfl_xor_sync(0xffffffffu, t, 2));
                redmax[cb * 128 + rb * 32 + mf * 16 + h2 * 8 + g] = t;
            }
        __syncthreads();
        float scale[2][2];
        #pragma unroll
        for (int mf = 0; mf < 2; ++mf)
            #pragma unroll
            for (int h2 = 0; h2 < 2; ++h2) {
                const int iL = rb * 32 + mf * 16 + h2 * 8 + g;
                float mt = fmaxf(redmax[iL], redmax[128 + iL]);
                float mn = fmaxf(mrun[mf][h2], mt);
                scale[mf][h2] = __expf(mrun[mf][h2] - mn);
                mrun[mf][h2] = mn;
            }
        float psum[2][2] = {{0.f, 0.f}, {0.f, 0.f}};
        #pragma unroll
        for (int mf = 0; mf < 2; ++mf)
            #pragma unroll
            for (int nf = 0; nf < 2; ++nf)
                #pragma unroll
                for (int e = 0; e < 4; ++e) {
                    const int h2 = e >> 1, jj = e & 1;
                    const int iL = rb * 32 + mf * 16 + h2 * 8 + g;
                    const int jL = cb * 16 + nf * 8 + 2 * c2 + jj;
                    float p = __expf(pv[mf][nf][e] - mrun[mf][h2]);
                    psum[mf][h2] += p;
                    smb[OFF_P + iL * 33 + jL] = f2tf32(p);
                }
        #pragma unroll
        for (int mf = 0; mf < 2; ++mf)
            #pragma unroll
            for (int h2 = 0; h2 < 2; ++h2) {
                float s = psum[mf][h2];
                s += __shfl_xor_sync(0xffffffffu, s, 1);
                s += __shfl_xor_sync(0xffffffffu, s, 2);
                redsum[cb * 128 + rb * 32 + mf * 16 + h2 * 8 + g] = s;
            }
        __syncthreads();
        #pragma unroll
        for (int mf = 0; mf < 2; ++mf)
            #pragma unroll
            for (int h2 = 0; h2 < 2; ++h2) {
                const int iL = rb * 32 + mf * 16 + h2 * 8 + g;
                lrun[mf][h2] = lrun[mf][h2] * scale[mf][h2] + redsum[iL] + redsum[128 + iL];
            }
        // rescale O
        #pragma unroll
        for (int mf = 0; mf < 2; ++mf)
            #pragma unroll
            for (int nf = 0; nf < 8; ++nf)
                #pragma unroll
                for (int e = 0; e < 4; ++e) Of[mf][nf][e] *= scale[mf][e >> 1];
        // AV: O += P @ H^T
        #pragma unroll
        for (int s = 0; s < 4; ++s) {
            uint32_t a[2][4];
            #pragma unroll
            for (int mf = 0; mf < 2; ++mf) {
                const int rbase = rb * 32 + mf * 16 + g;
                a[mf][0] = smb[OFF_P + rbase * 33 + 8 * s + c2];
                a[mf][1] = smb[OFF_P + (rbase + 8) * 33 + 8 * s + c2];
                a[mf][2] = smb[OFF_P + rbase * 33 + 8 * s + c2 + 4];
                a[mf][3] = smb[OFF_P + (rbase + 8) * 33 + 8 * s + c2 + 4];
            }
            #pragma unroll
            for (int nf = 0; nf < 8; ++nf) {
                const int r = cb * 64 + nf * 8 + g;
                uint32_t b0 = smb[OFF_B2 + r * 33 + 8 * s + c2];
                uint32_t b1 = smb[OFF_B2 + r * 33 + 8 * s + c2 + 4];
                mma8(Of[0][nf], a[0][0], a[0][1], a[0][2], a[0][3], b0, b1);
                mma8(Of[1][nf], a[1][0], a[1][1], a[1][2], a[1][3], b0, b1);
            }
        }
    }

    // write split partials
    #pragma unroll
    for (int mf = 0; mf < 2; ++mf)
        #pragma unroll
        for (int nf = 0; nf < 8; ++nf)
            #pragma unroll
            for (int e = 0; e < 4; ++e) {
                const int i = i0 + rb * 32 + mf * 16 + (e >> 1) * 8 + g;
                const int dd = cb * 64 + nf * 8 + 2 * c2 + (e & 1);
                g_Opart[((size_t)split * NN + i) * DD + dd] = Of[mf][nf][e];
            }
    if (cb == 0 && c2 == 0) {
        #pragma unroll
        for (int mf = 0; mf < 2; ++mf)
            #pragma unroll
            for (int h2 = 0; h2 < 2; ++h2) {
                const int i = i0 + rb * 32 + mf * 16 + h2 * 8 + g;
                g_m[split * NN + i] = mrun[mf][h2];
                g_l[split * NN + i] = lrun[mf][h2];
            }
    }
}

__global__ void combine2(float* __restrict__ OUT) {
    const int i = blockIdx.x, d = threadIdx.x;
    float M = -INFINITY;
    #pragma unroll
    for (int s = 0; s < NSPLIT; ++s) M = fmaxf(M, g_m[s * NN + i]);
    float num = 0.f, den = 0.f;
    #pragma unroll
    for (int s = 0; s < NSPLIT; ++s) {
        float w = __expf(g_m[s * NN + i] - M);
        den += w * g_l[s * NN + i];
        num += w * g_Opart[((size_t)s * NN + i) * DD + d];
    }
    OUT[i * DD + d] = num / den;
}

extern "C" void kernel_launch(void* const* d_in, const int* in_sizes, int n_in,
                              void* d_out, int out_size) {
    const float* H = nullptr; const int* ADJ = nullptr;
    const float* W = nullptr; const float* Bv = nullptr;
    for (int i = 0; i < n_in; ++i) {
        switch (in_sizes[i]) {
            case NN*DD:    H   = (const float*)d_in[i]; break;
            case 16777216: ADJ = (const int*)d_in[i]; break;   // NN*NN
            case 4*DD:     W   = (const float*)d_in[i]; break;
            case 4:        Bv  = (const float*)d_in[i]; break;
        }
    }
    cudaFuncSetAttribute(agg1, cudaFuncAttributeMaxDynamicSharedMemorySize, SMEM_BYTES);
    agg1<<<32 * NSPLIT, NT, SMEM_BYTES>>>(H, ADJ, W, Bv);
    combine2<<<NN, DD>>>((float*)d_out);
}

// round 7
// speedup vs baseline: 5.3998x; 1.7284x over previous
#include <cuda_runtime.h>
#include <cuda_fp16.h>
#include <math.h>
#include <stdint.h>

#define NN 4096
#define DD 128
#define NSPLIT 4
#define JSPAN 1024
#define TILES 32
#define NT 256

// u32-unit smem offsets
#define S_A    0                    // 128 x 68
#define S_B1   8704                 // 2 x 128 x 68
#define S_B2   26112                // 2 x 128 x 20
#define S_P    31232                // 128 x 20
#define S_ADJ  33792                // 2 x 128 x 32 (raw ints)
#define S_RMAX 41984
#define S_RSUM 42240
#define SMEM_U32 42496
#define SMEM_BYTES (SMEM_U32*4)     // 169984

__device__ __half g_HW[(size_t)4*NN*DD];
__device__ __half g_Hh[(size_t)NN*DD];
__device__ __half g_HT[(size_t)DD*NN];
__device__ float g_Opart[(size_t)NSPLIT*NN*DD];
__device__ float g_m[NSPLIT*NN];
__device__ float g_l[NSPLIT*NN];

__device__ __forceinline__ uint32_t smem_u32(const void* p) {
    uint32_t a;
    asm("{ .reg .u64 t; cvta.to.shared.u64 t, %1; cvt.u32.u64 %0, t; }" : "=r"(a) : "l"(p));
    return a;
}
__device__ __forceinline__ void cpa(uint32_t s, const void* g) {
    asm volatile("cp.async.cg.shared.global [%0], [%1], 16;" :: "r"(s), "l"(g) : "memory");
}
#define CP_COMMIT() asm volatile("cp.async.commit_group;" ::: "memory")

__device__ __forceinline__ void mma16(float* d, uint32_t a0, uint32_t a1, uint32_t a2,
                                      uint32_t a3, uint32_t b0, uint32_t b1) {
    asm volatile("mma.sync.aligned.m16n8k16.row.col.f32.f16.f16.f32 "
        "{%0,%1,%2,%3},{%4,%5,%6,%7},{%8,%9},{%0,%1,%2,%3};"
        : "+f"(d[0]), "+f"(d[1]), "+f"(d[2]), "+f"(d[3])
        : "r"(a0), "r"(a1), "r"(a2), "r"(a3), "r"(b0), "r"(b1));
}

// ---------------- prep: fp16 operand materialization ----------------
__global__ void prepH(const float* __restrict__ H, const float* __restrict__ W) {
    __shared__ __half sh[128 * 128];
    const int j0 = blockIdx.x * 128;
    const int jj = threadIdx.x >> 1, hf = threadIdx.x & 1;
    const int j = j0 + jj;
    const float* hr = H + (size_t)j * DD + hf * 64;
    #pragma unroll
    for (int q = 0; q < 16; ++q) {
        float4 v = *reinterpret_cast<const float4*>(hr + 4 * q);
        int d = hf * 64 + 4 * q;
        __half2 p0 = __floats2half2_rn(v.x, v.y), p1 = __floats2half2_rn(v.z, v.w);
        reinterpret_cast<__half2*>(g_Hh)[((size_t)j * DD + d) >> 1] = p0;
        reinterpret_cast<__half2*>(g_Hh)[(((size_t)j * DD + d) >> 1) + 1] = p1;
        sh[jj * 128 + d + 0] = __low2half(p0);  sh[jj * 128 + d + 1] = __high2half(p0);
        sh[jj * 128 + d + 2] = __low2half(p1);  sh[jj * 128 + d + 3] = __high2half(p1);
        #pragma unroll
        for (int k = 0; k < 4; ++k) {
            float4 wv = *reinterpret_cast<const float4*>(W + k * DD + d);
            __half2 a = __floats2half2_rn(v.x * wv.x, v.y * wv.y);
            __half2 b = __floats2half2_rn(v.z * wv.z, v.w * wv.w);
            size_t base = (((size_t)k * NN + j) * DD + d) >> 1;
            reinterpret_cast<__half2*>(g_HW)[base] = a;
            reinterpret_cast<__half2*>(g_HW)[base + 1] = b;
        }
    }
    __syncthreads();
    const int d2 = threadIdx.x >> 1, jh = threadIdx.x & 1;
    #pragma unroll
    for (int t = 0; t < 32; ++t) {
        int jl = jh * 64 + 2 * t;
        __half2 p = __halves2half2(sh[jl * 128 + d2], sh[(jl + 1) * 128 + d2]);
        reinterpret_cast<__half2*>(g_HT)[((size_t)d2 * NN + j0 + jl) >> 1] = p;
    }
}

// ---------------- main fused kernel ----------------
__global__ __launch_bounds__(NT, 1)
void agg1(const int* __restrict__ ADJ, const float* __restrict__ Bv) {
    extern __shared__ uint32_t smb[];
    const uint32_t sb4 = smem_u32(smb);
    const int tid = threadIdx.x, wid = tid >> 5, lane = tid & 31;
    const int g = lane >> 2, c2 = lane & 3;
    const int rb = wid & 3, cb = wid >> 2;
    const int itile = blockIdx.x & 31, split = blockIdx.x >> 5;
    const int i0 = itile * 128, jbase = split * JSPAN;

    const float bb0 = Bv[0], bb1 = Bv[1], bb2 = Bv[2], bb3 = Bv[3];
    float* redmax = reinterpret_cast<float*>(smb + S_RMAX);
    float* redsum = reinterpret_cast<float*>(smb + S_RSUM);

    // issue A (once) + tile 0 into stage 0
    {
        #pragma unroll
        for (int q = 0; q < 8; ++q) {
            int c = q * NT + tid, row = c >> 4, ch = c & 15;
            cpa(sb4 + (S_A + row * 68 + ch * 4) * 4, g_Hh + (size_t)(i0 + row) * DD + ch * 8);
        }
        const int j0 = jbase;
        #pragma unroll
        for (int q = 0; q < 8; ++q) {
            int c = q * NT + tid, row = c >> 4, ch = c & 15;
            cpa(sb4 + (S_B1 + row * 68 + ch * 4) * 4,
                g_HW + ((size_t)(row >> 5) * NN + j0 + (row & 31)) * DD + ch * 8);
        }
        #pragma unroll
        for (int q = 0; q < 2; ++q) {
            int c = q * NT + tid, d = c >> 2, ch = c & 3;
            cpa(sb4 + (S_B2 + d * 20 + ch * 4) * 4, g_HT + (size_t)d * NN + j0 + ch * 8);
        }
        #pragma unroll
        for (int q = 0; q < 4; ++q) {
            int c = q * NT + tid, i = c >> 3, ch = c & 7;
            cpa(sb4 + (S_ADJ + i * 32 + ch * 4) * 4, ADJ + (size_t)(i0 + i) * NN + j0 + ch * 4);
        }
    }
    CP_COMMIT();

    float mrun[2][2], lrun[2][2];
    #pragma unroll
    for (int a = 0; a < 2; ++a)
        #pragma unroll
        for (int b = 0; b < 2; ++b) { mrun[a][b] = -INFINITY; lrun[a][b] = 0.f; }
    float Of[2][8][4];
    #pragma unroll
    for (int mf = 0; mf < 2; ++mf)
        #pragma unroll
        for (int nf = 0; nf < 8; ++nf)
            #pragma unroll
            for (int e = 0; e < 4; ++e) Of[mf][nf][e] = 0.f;

    for (int tt = 0; tt < TILES; ++tt) {
        const int st = tt & 1;
        // prefetch next tile into other stage
        if (tt + 1 < TILES) {
            const int j0n = jbase + (tt + 1) * 32;
            const int sn = st ^ 1;
            #pragma unroll
            for (int q = 0; q < 8; ++q) {
                int c = q * NT + tid, row = c >> 4, ch = c & 15;
                cpa(sb4 + (S_B1 + sn * 8704 + row * 68 + ch * 4) * 4,
                    g_HW + ((size_t)(row >> 5) * NN + j0n + (row & 31)) * DD + ch * 8);
            }
            #pragma unroll
            for (int q = 0; q < 2; ++q) {
                int c = q * NT + tid, d = c >> 2, ch = c & 3;
                cpa(sb4 + (S_B2 + sn * 2560 + d * 20 + ch * 4) * 4, g_HT + (size_t)d * NN + j0n + ch * 8);
            }
            #pragma unroll
            for (int q = 0; q < 4; ++q) {
                int c = q * NT + tid, i = c >> 3, ch = c & 7;
                cpa(sb4 + (S_ADJ + sn * 4096 + i * 32 + ch * 4) * 4,
                    ADJ + (size_t)(i0 + i) * NN + j0n + ch * 4);
            }
            CP_COMMIT();
            asm volatile("cp.async.wait_group 1;" ::: "memory");
        } else {
            asm volatile("cp.async.wait_group 0;" ::: "memory");
        }
        __syncthreads();

        const uint32_t* B1p = smb + S_B1 + st * 8704;
        const uint32_t* B2p = smb + S_B2 + st * 2560;
        const int* adjp = reinterpret_cast<const int*>(smb + S_ADJ + st * 4096);

        // ---- S GEMM (fp16, 4 k-accumulator sets), FULL K: 8 chunks x k16 = 128
        float acc[4][2][2][4];
        #pragma unroll
        for (int k = 0; k < 4; ++k)
            #pragma unroll
            for (int mf = 0; mf < 2; ++mf)
                #pragma unroll
                for (int nf = 0; nf < 2; ++nf)
                    #pragma unroll
                    for (int e = 0; e < 4; ++e) acc[k][mf][nf][e] = 0.f;

        #pragma unroll
        for (int kc = 0; kc < 8; ++kc) {
            const int base = 8 * kc + c2;
            uint32_t av[4][2];
            #pragma unroll
            for (int rg = 0; rg < 4; ++rg) {
                const uint32_t* r = smb + S_A + (rb * 32 + rg * 8 + g) * 68 + base;
                av[rg][0] = r[0]; av[rg][1] = r[4];
            }
            uint32_t bv[4][2][2];
            #pragma unroll
            for (int k = 0; k < 4; ++k)
                #pragma unroll
                for (int nf = 0; nf < 2; ++nf) {
                    const uint32_t* r = B1p + (k * 32 + cb * 16 + nf * 8 + g) * 68 + base;
                    bv[k][nf][0] = r[0]; bv[k][nf][1] = r[4];
                }
            #pragma unroll
            for (int k = 0; k < 4; ++k)
                #pragma unroll
                for (int mf = 0; mf < 2; ++mf)
                    #pragma unroll
                    for (int nf = 0; nf < 2; ++nf)
                        mma16(acc[k][mf][nf], av[2*mf][0], av[2*mf+1][0], av[2*mf][1],
                              av[2*mf+1][1], bv[k][nf][0], bv[k][nf][1]);
        }

        // ---- selection + leaky + mask + online softmax
        float pv[2][2][4], tmax[2][2] = {{-INFINITY, -INFINITY}, {-INFINITY, -INFINITY}};
        #pragma unroll
        for (int mf = 0; mf < 2; ++mf)
            #pragma unroll
            for (int nf = 0; nf < 2; ++nf)
                #pragma unroll
                for (int e = 0; e < 4; ++e) {
                    const int h2 = e >> 1, jj = e & 1;
                    const int iL = rb * 32 + mf * 16 + h2 * 8 + g;
                    const int jL = cb * 16 + nf * 8 + 2 * c2 + jj;
                    int a = adjp[iL * 32 + jL];
                    float s0 = acc[0][mf][nf][e] + bb0;
                    float s1 = acc[1][mf][nf][e] + bb1;
                    float s2 = acc[2][mf][nf][e] + bb2;
                    float s3 = acc[3][mf][nf][e] + bb3;
                    float s = (a == 1) ? s0 : (a == 2) ? s1 : (a == 3) ? s2 : s3;
                    s = (s > 0.f) ? s : 0.2f * s;
                    float val = (a == 0) ? -9e15f : s;
                    pv[mf][nf][e] = val;
                    tmax[mf][h2] = fmaxf(tmax[mf][h2], val);
                }
        #pragma unroll
        for (int mf = 0; mf < 2; ++mf)
            #pragma unroll
            for (int h2 = 0; h2 < 2; ++h2) {
                float t = tmax[mf][h2];
                t = fmaxf(t, __shfl_xor_sync(0xffffffffu, t, 1));
                t = fmaxf(t, __shfl_xor_sync(0xffffffffu, t, 2));
                redmax[cb * 128 + rb * 32 + mf * 16 + h2 * 8 + g] = t;
            }
        __syncthreads();
        float scale[2][2];
        #pragma unroll
        for (int mf = 0; mf < 2; ++mf)
            #pragma unroll
            for (int h2 = 0; h2 < 2; ++h2) {
                const int iL = rb * 32 + mf * 16 + h2 * 8 + g;
                float mt = fmaxf(redmax[iL], redmax[128 + iL]);
                float mn = fmaxf(mrun[mf][h2], mt);
                scale[mf][h2] = __expf(mrun[mf][h2] - mn);
                mrun[mf][h2] = mn;
            }
        float psum[2][2] = {{0.f, 0.f}, {0.f, 0.f}};
        #pragma unroll
        for (int mf = 0; mf < 2; ++mf)
            #pragma unroll
            for (int nf = 0; nf < 2; ++nf)
                #pragma unroll
                for (int h2 = 0; h2 < 2; ++h2) {
                    const int iL = rb * 32 + mf * 16 + h2 * 8 + g;
                    float p0 = __expf(pv[mf][nf][h2 * 2 + 0] - mrun[mf][h2]);
                    float p1 = __expf(pv[mf][nf][h2 * 2 + 1] - mrun[mf][h2]);
                    psum[mf][h2] += p0 + p1;
                    __half2 hp = __floats2half2_rn(p0, p1);
                    smb[S_P + iL * 20 + cb * 8 + nf * 4 + c2] = *reinterpret_cast<uint32_t*>(&hp);
                }
        #pragma unroll
        for (int mf = 0; mf < 2; ++mf)
            #pragma unroll
            for (int h2 = 0; h2 < 2; ++h2) {
                float s = psum[mf][h2];
                s += __shfl_xor_sync(0xffffffffu, s, 1);
                s += __shfl_xor_sync(0xffffffffu, s, 2);
                redsum[cb * 128 + rb * 32 + mf * 16 + h2 * 8 + g] = s;
            }
        __syncthreads();
        #pragma unroll
        for (int mf = 0; mf < 2; ++mf)
            #pragma unroll
            for (int h2 = 0; h2 < 2; ++h2) {
                const int iL = rb * 32 + mf * 16 + h2 * 8 + g;
                lrun[mf][h2] = lrun[mf][h2] * scale[mf][h2] + redsum[iL] + redsum[128 + iL];
            }
        // rescale O then AV: O += P @ H^T
        #pragma unroll
        for (int mf = 0; mf < 2; ++mf)
            #pragma unroll
            for (int nf = 0; nf < 8; ++nf)
                #pragma unroll
                for (int e = 0; e < 4; ++e) Of[mf][nf][e] *= scale[mf][e >> 1];
        #pragma unroll
        for (int kc2 = 0; kc2 < 2; ++kc2) {
            const int base = 8 * kc2 + c2;
            uint32_t ap[2][4];
            #pragma unroll
            for (int mf = 0; mf < 2; ++mf) {
                const uint32_t* r = smb + S_P + (rb * 32 + mf * 16 + g) * 20 + base;
                ap[mf][0] = r[0]; ap[mf][1] = r[160]; ap[mf][2] = r[4]; ap[mf][3] = r[164];
            }
            #pragma unroll
            for (int nf = 0; nf < 8; ++nf) {
                const uint32_t* r = B2p + (cb * 64 + nf * 8 + g) * 20 + base;
                uint32_t b0 = r[0], b1 = r[4];
                mma16(Of[0][nf], ap[0][0], ap[0][1], ap[0][2], ap[0][3], b0, b1);
                mma16(Of[1][nf], ap[1][0], ap[1][1], ap[1][2], ap[1][3], b0, b1);
            }
        }
        __syncthreads();   // stage fully consumed before its next prefetch
    }

    // write split partials
    #pragma unroll
    for (int mf = 0; mf < 2; ++mf)
        #pragma unroll
        for (int nf = 0; nf < 8; ++nf)
            #pragma unroll
            for (int e = 0; e < 4; ++e) {
                const int i = i0 + rb * 32 + mf * 16 + (e >> 1) * 8 + g;
                const int dd = cb * 64 + nf * 8 + 2 * c2 + (e & 1);
                g_Opart[((size_t)split * NN + i) * DD + dd] = Of[mf][nf][e];
            }
    if (cb == 0 && c2 == 0) {
        #pragma unroll
        for (int mf = 0; mf < 2; ++mf)
            #pragma unroll
            for (int h2 = 0; h2 < 2; ++h2) {
                const int i = i0 + rb * 32 + mf * 16 + h2 * 8 + g;
                g_m[split * NN + i] = mrun[mf][h2];
                g_l[split * NN + i] = lrun[mf][h2];
            }
    }
}

__global__ void combine2(float* __restrict__ OUT) {
    const int i = blockIdx.x, d = threadIdx.x;
    float M = -INFINITY;
    #pragma unroll
    for (int s = 0; s < NSPLIT; ++s) M = fmaxf(M, g_m[s * NN + i]);
    float num = 0.f, den = 0.f;
    #pragma unroll
    for (int s = 0; s < NSPLIT; ++s) {
        float w = __expf(g_m[s * NN + i] - M);
        den += w * g_l[s * NN + i];
        num += w * g_Opart[((size_t)s * NN + i) * DD + d];
    }
    OUT[i * DD + d] = num / den;
}

extern "C" void kernel_launch(void* const* d_in, const int* in_sizes, int n_in,
                              void* d_out, int out_size) {
    const float* H = nullptr; const int* ADJ = nullptr;
    const float* W = nullptr; const float* Bv = nullptr;
    for (int i = 0; i < n_in; ++i) {
        switch (in_sizes[i]) {
            case NN*DD:    H   = (const float*)d_in[i]; break;
            case 16777216: ADJ = (const int*)d_in[i]; break;
            case 4*DD:     W   = (const float*)d_in[i]; break;
            case 4:        Bv  = (const float*)d_in[i]; break;
        }
    }
    prepH<<<32, 256>>>(H, W);
    cudaFuncSetAttribute(agg1, cudaFuncAttributeMaxDynamicSharedMemorySize, SMEM_BYTES);
    agg1<<<32 * NSPLIT, NT, SMEM_BYTES>>>(ADJ, Bv);
    combine2<<<NN, DD>>>((float*)d_out);
}

// round 8
// speedup vs baseline: 7.5090x; 1.3906x over previous
#include <cuda_runtime.h>
#include <cuda_fp16.h>
#include <math.h>
#include <stdint.h>

#define NN 4096
#define DD 128
#define NSPLIT 4
#define JSPAN 1024
#define TILES 32
#define NT 256

// u32-unit smem offsets
#define S_A    0                      // 128 rows x 72
#define S_B1   9216                   // 2 stages x 128 x 72
#define S_B2   27648                  // 2 stages x 128 x 40
#define S_ADJ  37888                  // 2 stages x 128 x 32 (ints, 16B-swizzled)
#define SMEM_U32 46080
#define SMEM_BYTES (SMEM_U32*4)       // 184320

__device__ __half g_HW[(size_t)4*NN*DD];
__device__ __half g_Hh[(size_t)NN*DD];
__device__ __half g_HT[(size_t)DD*NN];
__device__ float g_Opart[(size_t)NSPLIT*NN*DD];
__device__ float g_m[NSPLIT*NN];
__device__ float g_l[NSPLIT*NN];

__device__ __forceinline__ uint32_t smem_u32(const void* p) {
    uint32_t a;
    asm("{ .reg .u64 t; cvta.to.shared.u64 t, %1; cvt.u32.u64 %0, t; }" : "=r"(a) : "l"(p));
    return a;
}
__device__ __forceinline__ void cpa(uint32_t s, const void* g) {
    asm volatile("cp.async.cg.shared.global [%0], [%1], 16;" :: "r"(s), "l"(g) : "memory");
}
#define CP_COMMIT() asm volatile("cp.async.commit_group;" ::: "memory")
__device__ __forceinline__ uint32_t h2u(float a, float b) {
    __half2 h = __floats2half2_rn(a, b);
    return *reinterpret_cast<uint32_t*>(&h);
}
__device__ __forceinline__ void mma16(float* d, uint32_t a0, uint32_t a1, uint32_t a2,
                                      uint32_t a3, uint32_t b0, uint32_t b1) {
    asm volatile("mma.sync.aligned.m16n8k16.row.col.f32.f16.f16.f32 "
        "{%0,%1,%2,%3},{%4,%5,%6,%7},{%8,%9},{%0,%1,%2,%3};"
        : "+f"(d[0]), "+f"(d[1]), "+f"(d[2]), "+f"(d[3])
        : "r"(a0), "r"(a1), "r"(a2), "r"(a3), "r"(b0), "r"(b1));
}
// fragment interleave: within each 16-half k-chunk, u32 slot for pair c = 2*(c&3)+(c>>2)
__device__ __forceinline__ int islot(int c) { return 2 * (c & 3) + (c >> 2); }

// ---------------- prep: Hh + HW (fragment-interleaved rows) ----------------
__global__ void prep1(const float* __restrict__ H, const float* __restrict__ W) {
    const int t = blockIdx.x * 256 + threadIdx.x;       // 131072 threads
    const int j = t >> 5, dq = t & 31, d = dq * 4;
    float4 v = *reinterpret_cast<const float4*>(H + (size_t)j * DD + d);
    const int q = d >> 4, c0 = (d & 15) >> 1;
    const int s0 = q * 8 + islot(c0), s1 = q * 8 + islot(c0 + 1);
    uint32_t* Hh = reinterpret_cast<uint32_t*>(g_Hh);
    Hh[(size_t)j * 64 + s0] = h2u(v.x, v.y);
    Hh[(size_t)j * 64 + s1] = h2u(v.z, v.w);
    uint32_t* HWp = reinterpret_cast<uint32_t*>(g_HW);
    #pragma unroll
    for (int k = 0; k < 4; ++k) {
        float4 wv = *reinterpret_cast<const float4*>(W + k * DD + d);
        size_t base = ((size_t)k * NN + j) * 64;
        HWp[base + s0] = h2u(v.x * wv.x, v.y * wv.y);
        HWp[base + s1] = h2u(v.z * wv.z, v.w * wv.w);
    }
}

// ---------------- prep: HT (transpose, fragment-interleaved along j) --------
__global__ void prepT(const float* __restrict__ H) {
    __shared__ __half sh[32 * 128];
    const int j0 = blockIdx.x * 32, t = threadIdx.x;
    #pragma unroll
    for (int r = 0; r < 4; ++r) {
        int idx = r * 256 + t, jl = idx >> 5, dq = idx & 31;
        float4 v = *reinterpret_cast<const float4*>(H + (size_t)(j0 + jl) * DD + 4 * dq);
        __half2* dst = reinterpret_cast<__half2*>(sh + jl * 128 + 4 * dq);
        dst[0] = __floats2half2_rn(v.x, v.y);
        dst[1] = __floats2half2_rn(v.z, v.w);
    }
    __syncthreads();
    const int d = t >> 1, ql = t & 1;
    uint32_t* HT = reinterpret_cast<uint32_t*>(g_HT);
    #pragma unroll
    for (int c = 0; c < 8; ++c) {
        int jl = ql * 16 + 2 * c;
        uint32_t pp = h2u(__half2float(sh[jl * 128 + d]), __half2float(sh[(jl + 1) * 128 + d]));
        HT[(size_t)d * 2048 + (j0 >> 4) * 8 + ql * 8 + islot(c)] = pp;
    }
}

// ---------------- main fused kernel ----------------
__global__ __launch_bounds__(NT, 1)
void agg1(const int* __restrict__ ADJ, const float* __restrict__ Bv) {
    extern __shared__ uint32_t smb[];
    const uint32_t sb4 = smem_u32(smb);
    const int tid = threadIdx.x, wid = tid >> 5, lane = tid & 31;
    const int g = lane >> 2, c2 = lane & 3;
    const int itile = blockIdx.x & 31, split = blockIdx.x >> 5;
    const int i0 = itile * 128, jbase = split * JSPAN;
    const float bb0 = Bv[0], bb1 = Bv[1], bb2 = Bv[2], bb3 = Bv[3];

    // issue A (once) + tile 0 into stage 0
    #pragma unroll
    for (int q = 0; q < 8; ++q) {
        int c = q * NT + tid, row = c >> 4, ch = c & 15;
        cpa(sb4 + (S_A + row * 72 + ch * 4) * 4, g_Hh + (size_t)(i0 + row) * DD + ch * 8);
    }
    {
        const int j0 = jbase;
        #pragma unroll
        for (int q = 0; q < 8; ++q) {
            int c = q * NT + tid, row = c >> 4, ch = c & 15;
            cpa(sb4 + (S_B1 + row * 72 + ch * 4) * 4,
                g_HW + ((size_t)(row >> 5) * NN + j0 + (row & 31)) * DD + ch * 8);
        }
        #pragma unroll
        for (int q = 0; q < 2; ++q) {
            int c = q * NT + tid, d = c >> 2, ch = c & 3;
            cpa(sb4 + (S_B2 + d * 40 + ch * 4) * 4, g_HT + (size_t)d * NN + j0 + ch * 8);
        }
        #pragma unroll
        for (int q = 0; q < 4; ++q) {
            int c = q * NT + tid, i = c >> 3, ch = c & 7, ch2 = ch ^ ((i & 3) << 1);
            cpa(sb4 + (S_ADJ + i * 32 + ch2 * 4) * 4, ADJ + (size_t)(i0 + i) * NN + j0 + ch * 4);
        }
    }
    CP_COMMIT();

    float mrun[2] = {-INFINITY, -INFINITY}, lrun[2] = {0.f, 0.f};
    float Of[16][4];
    #pragma unroll
    for (int nf2 = 0; nf2 < 16; ++nf2)
        #pragma unroll
        for (int e = 0; e < 4; ++e) Of[nf2][e] = 0.f;

    const int rA = (wid * 16 + g) * 72 + 2 * c2;        // A row-g base (u32)
    const int rAh = rA + 8 * 72;                        // A row g+8

    for (int tt = 0; tt < TILES; ++tt) {
        const int st = tt & 1;
        if (tt + 1 < TILES) {
            const int j0n = jbase + (tt + 1) * 32, sn = st ^ 1;
            #pragma unroll
            for (int q = 0; q < 8; ++q) {
                int c = q * NT + tid, row = c >> 4, ch = c & 15;
                cpa(sb4 + (S_B1 + sn * 9216 + row * 72 + ch * 4) * 4,
                    g_HW + ((size_t)(row >> 5) * NN + j0n + (row & 31)) * DD + ch * 8);
            }
            #pragma unroll
            for (int q = 0; q < 2; ++q) {
                int c = q * NT + tid, d = c >> 2, ch = c & 3;
                cpa(sb4 + (S_B2 + sn * 5120 + d * 40 + ch * 4) * 4,
                    g_HT + (size_t)d * NN + j0n + ch * 8);
            }
            #pragma unroll
            for (int q = 0; q < 4; ++q) {
                int c = q * NT + tid, i = c >> 3, ch = c & 7, ch2 = ch ^ ((i & 3) << 1);
                cpa(sb4 + (S_ADJ + sn * 4096 + i * 32 + ch2 * 4) * 4,
                    ADJ + (size_t)(i0 + i) * NN + j0n + ch * 4);
            }
            CP_COMMIT();
            asm volatile("cp.async.wait_group 1;" ::: "memory");
        } else {
            asm volatile("cp.async.wait_group 0;" ::: "memory");
        }
        __syncthreads();

        const uint32_t* B1p = smb + S_B1 + st * 9216;
        const uint32_t* B2p = smb + S_B2 + st * 5120;
        const int* adjp = reinterpret_cast<const int*>(smb + S_ADJ + st * 4096);

        // ---- S GEMM: warp owns 16 i-rows x full 32 j, 4 k-sets
        float acc[4][4][4];
        #pragma unroll
        for (int k = 0; k < 4; ++k)
            #pragma unroll
            for (int nf = 0; nf < 4; ++nf)
                #pragma unroll
                for (int e = 0; e < 4; ++e) acc[k][nf][e] = 0.f;

        #pragma unroll
        for (int kc = 0; kc < 8; ++kc) {
            uint2 aLo = *reinterpret_cast<const uint2*>(smb + rA + 8 * kc);
            uint2 aHi = *reinterpret_cast<const uint2*>(smb + rAh + 8 * kc);
            #pragma unroll
            for (int k = 0; k < 4; ++k)
                #pragma unroll
                for (int nf = 0; nf < 4; ++nf) {
                    uint2 b = *reinterpret_cast<const uint2*>(
                        B1p + (k * 32 + nf * 8 + g) * 72 + 8 * kc + 2 * c2);
                    mma16(acc[k][nf], aLo.x, aHi.x, aLo.y, aHi.y, b.x, b.y);
                }
        }

        // ---- selection + leaky + mask (all in registers)
        float pv[4][4], tmax[2] = {-INFINITY, -INFINITY};
        #pragma unroll
        for (int nf = 0; nf < 4; ++nf) {
            int u = (2 * nf + (c2 >> 1)) ^ ((g & 3) << 1);
            int col = u * 4 + 2 * (c2 & 1);
            int2 ajL = *reinterpret_cast<const int2*>(adjp + (wid * 16 + g) * 32 + col);
            int2 ajH = *reinterpret_cast<const int2*>(adjp + (wid * 16 + 8 + g) * 32 + col);
            #pragma unroll
            for (int e = 0; e < 4; ++e) {
                int a = (e & 1) ? ((e < 2) ? ajL.y : ajH.y) : ((e < 2) ? ajL.x : ajH.x);
                float s0 = acc[0][nf][e] + bb0;
                float s1 = acc[1][nf][e] + bb1;
                float s2 = acc[2][nf][e] + bb2;
                float s3 = acc[3][nf][e] + bb3;
                float s = (a == 1) ? s0 : (a == 2) ? s1 : (a == 3) ? s2 : s3;
                s = (s > 0.f) ? s : 0.2f * s;
                float val = (a == 0) ? -9e15f : s;
                pv[nf][e] = val;
                tmax[e >> 1] = fmaxf(tmax[e >> 1], val);
            }
        }
        // ---- online softmax: intra-warp (c2 group) only
        float scale[2];
        #pragma unroll
        for (int h2 = 0; h2 < 2; ++h2) {
            float t = tmax[h2];
            t = fmaxf(t, __shfl_xor_sync(0xffffffffu, t, 1));
            t = fmaxf(t, __shfl_xor_sync(0xffffffffu, t, 2));
            float mn = fmaxf(mrun[h2], t);
            scale[h2] = __expf(mrun[h2] - mn);
            mrun[h2] = mn;
        }
        float psum[2] = {0.f, 0.f};
        uint32_t ph[4][2];
        #pragma unroll
        for (int nf = 0; nf < 4; ++nf)
            #pragma unroll
            for (int h2 = 0; h2 < 2; ++h2) {
                float p0 = __expf(pv[nf][2 * h2 + 0] - mrun[h2]);
                float p1 = __expf(pv[nf][2 * h2 + 1] - mrun[h2]);
                psum[h2] += p0 + p1;
                ph[nf][h2] = h2u(p0, p1);
            }
        #pragma unroll
        for (int h2 = 0; h2 < 2; ++h2) {
            float s = psum[h2];
            s += __shfl_xor_sync(0xffffffffu, s, 1);
            s += __shfl_xor_sync(0xffffffffu, s, 2);
            lrun[h2] = lrun[h2] * scale[h2] + s;
        }
        // ---- rescale O, then AV with P as in-register A fragments
        #pragma unroll
        for (int nf2 = 0; nf2 < 16; ++nf2)
            #pragma unroll
            for (int e = 0; e < 4; ++e) Of[nf2][e] *= scale[e >> 1];
        #pragma unroll
        for (int kc2 = 0; kc2 < 2; ++kc2) {
            uint32_t a0 = ph[2 * kc2][0], a1 = ph[2 * kc2][1];
            uint32_t a2 = ph[2 * kc2 + 1][0], a3 = ph[2 * kc2 + 1][1];
            #pragma unroll
            for (int nf2 = 0; nf2 < 16; ++nf2) {
                uint2 b = *reinterpret_cast<const uint2*>(
                    B2p + (nf2 * 8 + g) * 40 + 8 * kc2 + 2 * c2);
                mma16(Of[nf2], a0, a1, a2, a3, b.x, b.y);
            }
        }
        __syncthreads();   // stage consumed before next prefetch overwrites it
    }

    // write split partials
    #pragma unroll
    for (int nf2 = 0; nf2 < 16; ++nf2)
        #pragma unroll
        for (int e = 0; e < 4; ++e) {
            const int i = i0 + wid * 16 + (e >> 1) * 8 + g;
            const int dd = nf2 * 8 + 2 * c2 + (e & 1);
            g_Opart[((size_t)split * NN + i) * DD + dd] = Of[nf2][e];
        }
    if (c2 == 0) {
        #pragma unroll
        for (int h2 = 0; h2 < 2; ++h2) {
            const int i = i0 + wid * 16 + h2 * 8 + g;
            g_m[split * NN + i] = mrun[h2];
            g_l[split * NN + i] = lrun[h2];
        }
    }
}

__global__ void combine2(float* __restrict__ OUT) {
    const int gid = blockIdx.x * 256 + threadIdx.x;     // 131072
    const int i = gid >> 5, dq = gid & 31;
    float M = -INFINITY;
    #pragma unroll
    for (int s = 0; s < NSPLIT; ++s) M = fmaxf(M, g_m[s * NN + i]);
    float den = 0.f;
    float4 num = make_float4(0.f, 0.f, 0.f, 0.f);
    #pragma unroll
    for (int s = 0; s < NSPLIT; ++s) {
        float w = __expf(g_m[s * NN + i] - M);
        den += w * g_l[s * NN + i];
        float4 o = *reinterpret_cast<const float4*>(
            &g_Opart[((size_t)s * NN + i) * DD + 4 * dq]);
        num.x += w * o.x; num.y += w * o.y; num.z += w * o.z; num.w += w * o.w;
    }
    float inv = 1.f / den;
    *reinterpret_cast<float4*>(&OUT[(size_t)i * DD + 4 * dq]) =
        make_float4(num.x * inv, num.y * inv, num.z * inv, num.w * inv);
}

extern "C" void kernel_launch(void* const* d_in, const int* in_sizes, int n_in,
                              void* d_out, int out_size) {
    const float* H = nullptr; const int* ADJ = nullptr;
    const float* W = nullptr; const float* Bv = nullptr;
    for (int i = 0; i < n_in; ++i) {
        switch (in_sizes[i]) {
            case NN*DD:    H   = (const float*)d_in[i]; break;
            case 16777216: ADJ = (const int*)d_in[i]; break;
            case 4*DD:     W   = (const float*)d_in[i]; break;
            case 4:        Bv  = (const float*)d_in[i]; break;
        }
    }
    prep1<<<512, 256>>>(H, W);
    prepT<<<128, 256>>>(H);
    cudaFuncSetAttribute(agg1, cudaFuncAttributeMaxDynamicSharedMemorySize, SMEM_BYTES);
    agg1<<<32 * NSPLIT, NT, SMEM_BYTES>>>(ADJ, Bv);
    combine2<<<512, 256>>>((float*)d_out);
}